// round 7
// baseline (speedup 1.0000x reference)
#include <cuda_runtime.h>

// Fused 6-layer ReLU RNN + FC + log_softmax, diagonal-wavefront persistent kernel.
// R7: 2 CTAs per SM for barrier/latency decoupling.
//     256 CTAs x 256 threads x 4 pairs. 240 layer lanes (6L x 20N x 2 groups,
//     2 pairs/thread), 8 fc lanes + 8 softmax lanes in warp 7.
//     All weights in registers (pre-duplicated f32x2); h-state only in SMEM.

#define TT 1024
#define BB 2048
#define HH 20
#define LL 6
#define PP 4          // batch-pairs per CTA (pair = 2 batch elems packed f32x2)
#define PSTR 22       // padded h-row stride in 8B units (16B-aligned rows)
#define NTH 256
#define NCTA 256

typedef unsigned long long u64;

__device__ __forceinline__ u64 f2fma(u64 a, u64 b, u64 c) {
    u64 r; asm("fma.rn.f32x2 %0, %1, %2, %3;" : "=l"(r) : "l"(a), "l"(b), "l"(c)); return r;
}
__device__ __forceinline__ u64 f2add(u64 a, u64 b) {
    u64 r; asm("add.rn.f32x2 %0, %1, %2;" : "=l"(r) : "l"(a), "l"(b)); return r;
}
__device__ __forceinline__ u64 dup2(float x) {
    u64 r; asm("mov.b64 %0, {%1, %1};" : "=l"(r) : "f"(x)); return r;
}
__device__ __forceinline__ u64 pk2(float lo, float hi) {
    u64 r; asm("mov.b64 %0, {%1, %2};" : "=l"(r) : "f"(lo), "f"(hi)); return r;
}
__device__ __forceinline__ void unpk(u64 a, float& lo, float& hi) {
    asm("mov.b64 {%0, %1}, %2;" : "=f"(lo), "=f"(hi) : "l"(a));
}

// 20-element f32x2 dot product: weights from register array, h from SMEM.
__device__ __forceinline__ u64 dot20(const u64 (&w)[HH], const u64* hbase, u64 acc) {
    const ulonglong2* h = (const ulonglong2*)hbase;
    u64 a0 = acc, a1 = 0ull, a2 = 0ull, a3 = 0ull;
#pragma unroll
    for (int q = 0; q < 5; q++) {
        ulonglong2 h0 = h[q], h1 = h[q + 5];
        a0 = f2fma(w[2 * q],      h0.x, a0);
        a1 = f2fma(w[2 * q + 1],  h0.y, a1);
        a2 = f2fma(w[2 * q + 10], h1.x, a2);
        a3 = f2fma(w[2 * q + 11], h1.y, a3);
    }
    return f2add(f2add(a0, a1), f2add(a2, a3));
}

__global__ __launch_bounds__(NTH, 2) void rnn_wavefront_kernel(
    const float* __restrict__ x,     // [T, B, 2]
    const float* __restrict__ Wih0,  // [H, 2]
    const float* __restrict__ Wih,   // [L-1, H, H]
    const float* __restrict__ Whh,   // [L, H, H]
    const float* __restrict__ bih,   // [L, H]
    const float* __restrict__ bhh,   // [L, H]
    const float* __restrict__ fcw,   // [2, H]
    const float* __restrict__ fcb,   // [2]
    float* __restrict__ out)         // [T, B, 2]
{
    __shared__ __align__(16) u64 hb[2][LL][PP * PSTR];   // double-buffered h state (f32x2/neuron)
    __shared__ __align__(16) u64 logitb[2][PP][2];       // double-buffered logits

    const int tid = threadIdx.x;

    for (int i = tid; i < 2 * LL * PP * PSTR; i += NTH) ((u64*)hb)[i] = 0ull;
    for (int i = tid; i < 2 * PP * 2; i += NTH)         ((u64*)logitb)[i] = 0ull;

    // ---- role decomposition ----
    const bool is_layer = tid < 240;
    const int l  = tid / 40;              // layer (valid for layer lanes)
    const int u  = tid % 40;
    const int j  = u % 20;                // neuron
    const int ph = u / 20;                // 0..1
    const int p0 = ph, p1 = ph + 2;       // two pairs per lane

    const bool is_fc = (tid >= 240) && (tid < 248);
    const bool is_sm = (tid >= 248);
    const int fc_p = (tid - 240) >> 1;    // pair for fc lanes
    const int fc_c = tid & 1;             // class
    const int sm_p = (tid - 248) >> 1;    // pair for softmax lanes
    const int sm_w = tid & 1;             // which half of f32x2

    // ---- weights into registers (fc lanes overlay their weights on wh[]) ----
    u64 wh[HH];
    u64 wi[HH];
    u64 bj = 0ull;
#pragma unroll
    for (int k = 0; k < HH; k++) { wh[k] = 0ull; wi[k] = 0ull; }

    if (is_layer) {
#pragma unroll
        for (int k = 0; k < HH; k++) wh[k] = dup2(Whh[(l * HH + j) * HH + k]);
        if (l > 0) {
#pragma unroll
            for (int k = 0; k < HH; k++) wi[k] = dup2(Wih[((l - 1) * HH + j) * HH + k]);
        } else {
            wi[0] = dup2(Wih0[j * 2 + 0]);
            wi[1] = dup2(Wih0[j * 2 + 1]);
        }
        bj = dup2(bih[l * HH + j] + bhh[l * HH + j]);
    } else if (is_fc) {
#pragma unroll
        for (int k = 0; k < HH; k++) wh[k] = dup2(fcw[fc_c * HH + k]);
        bj = dup2(fcb[fc_c]);
    }

    // ---- layer-0 input staging ----
    const float2* __restrict__ x2 = (const float2*)x;   // x2[t*BB + b]
    float2 xa0, xb0, xa1, xb1;
    int b00 = 0, b01 = 0, b10 = 0, b11 = 0;
    if (is_layer && l == 0) {
        b00 = blockIdx.x * PP + p0; b01 = b00 + (BB / 2);
        b10 = blockIdx.x * PP + p1; b11 = b10 + (BB / 2);
        xa0 = x2[b00]; xb0 = x2[b01];
        xa1 = x2[b10]; xb1 = x2[b11];
    }

    __syncthreads();

    for (int tau = 0; tau < TT + 7; ++tau) {
        const int A = tau & 1;
        const u64(*rb)[PP * PSTR] = hb[A];       // read buffer (last tick)
        u64(*wb)[PP * PSTR] = hb[A ^ 1];         // write buffer (this tick)

        if (is_layer) {
            const int t = tau - l;
            if ((unsigned)t < TT) {
                // pair p0
                {
                    u64 s = dot20(wh, &rb[l][p0 * PSTR], bj);
                    if (l > 0) {
                        s = f2add(s, dot20(wi, &rb[l - 1][p0 * PSTR], 0ull));
                    } else {
                        s = f2add(s, f2add(f2fma(wi[0], pk2(xa0.x, xb0.x), 0ull),
                                           f2fma(wi[1], pk2(xa0.y, xb0.y), 0ull)));
                    }
                    float lo, hi; unpk(s, lo, hi);
                    lo = fmaxf(lo, 0.0f); hi = fmaxf(hi, 0.0f);
                    *(float2*)&wb[l][p0 * PSTR + j] = make_float2(lo, hi);
                }
                // pair p1
                {
                    u64 s = dot20(wh, &rb[l][p1 * PSTR], bj);
                    if (l > 0) {
                        s = f2add(s, dot20(wi, &rb[l - 1][p1 * PSTR], 0ull));
                    } else {
                        s = f2add(s, f2add(f2fma(wi[0], pk2(xa1.x, xb1.x), 0ull),
                                           f2fma(wi[1], pk2(xa1.y, xb1.y), 0ull)));
                    }
                    float lo, hi; unpk(s, lo, hi);
                    lo = fmaxf(lo, 0.0f); hi = fmaxf(hi, 0.0f);
                    *(float2*)&wb[l][p1 * PSTR + j] = make_float2(lo, hi);
                }
            }
            // prefetch next x for layer 0
            if (l == 0 && tau + 1 < TT) {
                const int tn = tau + 1;
                xa0 = x2[tn * BB + b00]; xb0 = x2[tn * BB + b01];
                xa1 = x2[tn * BB + b10]; xb1 = x2[tn * BB + b11];
            }
        } else if (is_fc) {
            // ---- fc: logits(t = tau - 6) ----
            if ((unsigned)(tau - 6) < TT) {
                logitb[A ^ 1][fc_p][fc_c] = dot20(wh, &rb[5][fc_p * PSTR], bj);
            }
        } else if (is_sm) {
            // ---- log_softmax + store, t = tau - 7 ----
            if ((unsigned)(tau - 7) < TT) {
                const int t = tau - 7;
                ulonglong2 lg = *(const ulonglong2*)&logitb[A][sm_p][0];
                float c0a, c0b, c1a, c1b;
                unpk(lg.x, c0a, c0b);   // class-0 logits for (b0, b1)
                unpk(lg.y, c1a, c1b);   // class-1 logits
                float u0 = sm_w ? c0b : c0a;
                float u1 = sm_w ? c1b : c1a;
                float m = fmaxf(u0, u1);
                float lse = m + __logf(1.0f + __expf(fminf(u0, u1) - m));
                const int pg = blockIdx.x * PP + sm_p;
                const int b = sm_w ? pg + (BB / 2) : pg;
                *(float2*)&out[(size_t)(t * BB + b) * 2] = make_float2(u0 - lse, u1 - lse);
            }
        }

        __syncthreads();
    }
}

extern "C" void kernel_launch(void* const* d_in, const int* in_sizes, int n_in,
                              void* d_out, int out_size) {
    const float* x    = (const float*)d_in[0];
    const float* Wih0 = (const float*)d_in[1];
    const float* Wih  = (const float*)d_in[2];
    const float* Whh  = (const float*)d_in[3];
    const float* bih  = (const float*)d_in[4];
    const float* bhh  = (const float*)d_in[5];
    const float* fcw  = (const float*)d_in[6];
    const float* fcb  = (const float*)d_in[7];
    float* out = (float*)d_out;

    rnn_wavefront_kernel<<<NCTA, NTH>>>(x, Wih0, Wih, Whh, bih, bhh, fcw, fcb, out);
}